// round 17
// baseline (speedup 1.0000x reference)
#include <cuda_runtime.h>
#include <cstdint>

#define NB   32
#define H    1024
#define W    1024
#define BH   73
#define BW   73
#define BS   14                  // block stride = 16 - 3 + 1
#define GRP  37                  // strip pairs: (g, g+37)
#define NROWS (NB*BH)            // 2336 flag rows
#define TOTAL (NB*BH*BW)         // 170528

__device__ unsigned long long g_acc;       // low32: count, high32: strips-done
__device__ unsigned g_winact[NROWS * 8];   // inactive-mask per (row, warp); zero-init

// window->warp partition (non-overlapping 32-chunk ranges):
// warp w owns windows [first(w), first(w+1)), first(w) = 9w + (w>=4)
__host__ __device__ __forceinline__ int warp_first(int w) {
    return 9 * w + (w >= 4 ? 1 : 0);
}

// ---------------------------------------------------------------------------
// Rare-path fixup (p ~ 2^-244): rebuild the whole output serially from
// g_winact (zero-init = active). Never executed in practice; correctness only.
// ---------------------------------------------------------------------------
__device__ __noinline__ void fixup(float* __restrict__ out, int total) {
    int off = 0, inoff = 0;
    for (int row = 0; row < NROWS; row++) {
        int i0 = row / BH, i1 = row - i0 * BH;
        for (int w = 0; w < 8; w++) {
            int first = warp_first(w), next = warp_first(w + 1);
            unsigned mi = g_winact[row * 8 + w];
            for (int l = 0; l < next - first; l++) {
                int t = first + l;
                if (!((mi >> l) & 1u)) {
                    int pos = off++;
                    out[3 * pos + 0] = (float)i0;
                    out[3 * pos + 1] = (float)i1;
                    out[3 * pos + 2] = (float)t;
                } else {
                    int pos = total + inoff++;
                    out[3 * pos + 0] = (float)NB;
                    out[3 * pos + 1] = (float)BH;
                    out[3 * pos + 2] = (float)BW;
                }
            }
        }
    }
}

// warp-local exact recompute of undecided windows (rare: p<=2^-8 per window)
__device__ __forceinline__ void slow_eval(const float* __restrict__ mbase,
                                          int by, int first, int lane,
                                          unsigned und, int* cnt, unsigned* inact) {
    const int r0 = by * BS - 1;           // may be -1 (zero pad)
    for (unsigned m = und; m; m &= m - 1) {
        int l0;
        asm("bfind.u32 %0, %1;" : "=r"(l0) : "r"(m & (0u - m)));  // ctz
        int tu = first + l0;
        int c0 = 14 * tu - 1;             // may be -1 only for tu==0
        int r  = r0 + (lane & 15);        // 16 rows, <= 1022
        int cb = c0 + ((lane >> 4) << 3);
        float mx = 0.f;
#pragma unroll
        for (int k = 0; k < 8; k++) {
            int c = cb + k;               // <= 1022
            if (r >= 0 && c >= 0) mx = fmaxf(mx, mbase[(size_t)r * W + c]);
        }
#pragma unroll
        for (int s = 16; s; s >>= 1) mx = fmaxf(mx, __shfl_xor_sync(0xffffffffu, mx, s));
        if (mx > 0.5f) (*cnt)++;
        else *inact |= 1u << l0;
    }
}

// ---------------------------------------------------------------------------
// Single fused kernel, TWO strips per CTA -> 1184 CTAs x 256 thr = 148x8 =
// ONE full wave. Warp-autonomous (no mid-kernel CTA barrier, no smem data):
//  - warp w loads chunk 32w+lane (= rowp[t]) of BOTH probe rows (g*14 and
//    (g+37)*14) -> 2 independent LDG.128 per thread (MLP=2).
//  - non-overlap partition: warp w owns windows [9w+(w>=4), ...); window
//    certified active if any of its in-warp contained chunks is hot
//    (3 chunks, or 2 for the 4 straddlers -> p_und 2^-12 / 2^-8).
//  - speculative triples (prefix 73*row) written in the load shadow;
//    threads 0..72 -> strip A, threads 128..200 -> strip B.
//  - lane0: one shared packed atomic; 8th arrival does the single global
//    release-atomic; global-last writes count, (never) fixup, resets.
// ---------------------------------------------------------------------------
__global__ __launch_bounds__(256, 8) void fused_kernel(const float* __restrict__ mask,
                                                       float* __restrict__ out,
                                                       int count_idx) {
    const int cta = blockIdx.x;           // n*GRP + g
    const int n  = cta / GRP;
    const int g  = cta - n * GRP;
    const int byA = g, byB = g + GRP;     // byB valid iff byB < BH (g < 36)
    const int nstrips = (byB < BH) ? 2 : 1;
    const int t  = threadIdx.x;
    const int w  = t >> 5, lane = t & 31;

    __shared__ unsigned s_pack;
    if (t == 0) s_pack = 0u;
    __syncthreads();                      // only barrier; before the loads

    const float* mbase = mask + (size_t)n * H * W;
    const float4* rowpA = (const float4*)mbase + (size_t)(byA * BS) * (W / 4);
    const float4* rowpB = (const float4*)mbase +
        (size_t)((nstrips == 2 ? byB : byA) * BS) * (W / 4);

    // ---- probe loads: 2 independent LDG.128 per thread ----
    float4 vA = rowpA[t];
    float4 vB = rowpB[t];

    // ---- speculative output triples in the load shadow ----
    const int rowA = n * BH + byA;
    if (t < BW) {
        float* o = out + (size_t)rowA * (3 * BW) + 3 * t;
        o[0] = (float)n; o[1] = (float)byA; o[2] = (float)t;
    } else if (nstrips == 2 && t >= 128 && t < 128 + BW) {
        int tb = t - 128;
        float* o = out + (size_t)(rowA + GRP) * (3 * BW) + 3 * tb;
        o[0] = (float)n; o[1] = (float)byB; o[2] = (float)tb;
    }

    // ---- chunk-hot ballots (warp-local; chunk index == t) ----
    int hotA = (vA.x > 0.5f) | (vA.y > 0.5f) | (vA.z > 0.5f) | (vA.w > 0.5f);
    int hotB = (vB.x > 0.5f) | (vB.y > 0.5f) | (vB.z > 0.5f) | (vB.w > 0.5f);
    unsigned BA = __ballot_sync(0xffffffffu, hotA);
    unsigned BB = __ballot_sync(0xffffffffu, hotB);

    // ---- per-warp window eval: lane l -> window first(w)+l ----
    const int first = warp_first(w);
    const int nw    = warp_first(w + 1) - first;   // 9 or 10
    const int tw    = first + lane;
    const int valid = lane < nw;
    unsigned m = 0u;
    if (valid) {
        int jlo = (14 * tw + 2) >> 2;     // first contained chunk
        int rel = jlo - (w << 5);         // -1 .. 30
        m = (rel < 0) ? (7u >> (-rel)) : (7u << rel);  // 2-3 chunk cert mask
    }
    unsigned undA = __ballot_sync(0xffffffffu, valid && !(BA & m));
    unsigned undB = __ballot_sync(0xffffffffu, valid && !(BB & m));
    int cntA = nw - __popc(undA);
    int cntB = (nstrips == 2) ? nw - __popc(undB) : 0;
    unsigned inactA = 0u, inactB = 0u;

    if (undA)                  slow_eval(mbase, byA, first, lane, undA, &cntA, &inactA);
    if (nstrips == 2 && undB)  slow_eval(mbase, byB, first, lane, undB, &cntB, &inactB);

    if (lane != 0) return;                // warp-decoupled retirement

    if (inactA | inactB) {                // never in practice
        if (inactA) g_winact[rowA * 8 + w] = inactA;
        if (inactB) g_winact[(rowA + GRP) * 8 + w] = inactB;
        __threadfence();
    }
    unsigned cnt = (unsigned)(cntA + cntB);
    unsigned old = atomicAdd(&s_pack, cnt | (1u << 16));
    if ((old >> 16) != 7u) return;        // not the CTA's last warp

    unsigned tot = (old & 0xffffu) + cnt;
    unsigned long long add = (unsigned long long)tot
                           | ((unsigned long long)nstrips << 32);
    unsigned long long o2;
    asm volatile("atom.add.release.gpu.u64 %0, [%1], %2;"
                 : "=l"(o2) : "l"(&g_acc), "l"(add) : "memory");
    if ((unsigned)(o2 >> 32) == (unsigned)(NROWS - nstrips)) {   // global-last
        unsigned grand = (unsigned)(o2 & 0xffffffffu) + tot;
        if (count_idx >= 0) out[count_idx] = (float)grand;
        if (grand != TOTAL) {
            asm volatile("fence.acquire.gpu;" ::: "memory");
            fixup(out, (int)grand);
        }
        g_acc = 0ull;                                 // reset for next replay
    }
}

extern "C" void kernel_launch(void* const* d_in, const int* in_sizes, int n_in,
                              void* d_out, int out_size) {
    const float* mask = (const float*)d_in[0];
    float* out = (float*)d_out;

    int count_idx = (out_size > 3 * TOTAL) ? (out_size - 1) : -1;

    fused_kernel<<<NB * GRP, 256>>>(mask, out, count_idx);
}